// round 17
// baseline (speedup 1.0000x reference)
#include <cuda_runtime.h>
#include <cuda_bf16.h>
#include <cuda_fp16.h>
#include <cstdint>
#include <math.h>

#define BB 16
#define CC 512
#define KK 32
#define HWN 4096
#define EPSF 1e-5f
#define NSPLIT 8

// ---------------- scratch (static device globals: no allocation) ----------------
__device__ __half g_fh[(size_t)BB * HWN * CC];     // feats fp16 (b,n,c) 67 MB
__device__ __half g_asnT[(size_t)BB * KK * HWN];   // assign^T fp16 (b,k,n) 4 MB
__device__ float g_c2[KK];                         // ||codeword||^2
__device__ float g_enc[BB * KK * CC];              // partial encoded
__device__ float g_asum[BB * KK];                  // sum_n assign
__device__ float g_gamma[BB * CC];
__device__ __half g_xh[(size_t)BB * HWN * CC];     // x^T (b,n,c) fp16  67 MB
__device__ __half g_wh[CC * CC];                   // conv_w fp16
__device__ __half g_cwh[KK * CC];                  // codewords fp16

// ---------------- helpers ----------------
__device__ __forceinline__ uint32_t smem_u32(const void* p) {
    uint32_t a;
    asm("{ .reg .u64 t; cvta.to.shared.u64 t, %1; cvt.u32.u64 %0, t; }" : "=r"(a) : "l"(p));
    return a;
}
__device__ __forceinline__ uint32_t swz64(uint32_t o)  { return o ^ ((o >> 3) & 0x30); }
__device__ __forceinline__ uint32_t swz128(uint32_t o) { return o ^ ((o >> 3) & 0x70); }
__device__ __forceinline__ uint32_t swz256(uint32_t o) { return o ^ ((o >> 4) & 0x70); }

__device__ __forceinline__ void cpasync16(uint32_t dst, const void* src) {
    asm volatile("cp.async.cg.shared.global [%0], [%1], 16;"
                 :: "r"(dst), "l"(__cvta_generic_to_global(src)) : "memory");
}
#define CP_COMMIT() asm volatile("cp.async.commit_group;" ::: "memory")
#define CP_WAIT2()  asm volatile("cp.async.wait_group 2;" ::: "memory")

__device__ __forceinline__ void ldsm4(uint32_t addr, uint32_t* r) {
    asm volatile("ldmatrix.sync.aligned.m8n8.x4.shared.b16 {%0,%1,%2,%3}, [%4];"
                 : "=r"(r[0]), "=r"(r[1]), "=r"(r[2]), "=r"(r[3]) : "r"(addr));
}
__device__ __forceinline__ void ldsm4t(uint32_t addr, uint32_t* r) {
    asm volatile("ldmatrix.sync.aligned.m8n8.x4.trans.shared.b16 {%0,%1,%2,%3}, [%4];"
                 : "=r"(r[0]), "=r"(r[1]), "=r"(r[2]), "=r"(r[3]) : "r"(addr));
}
__device__ __forceinline__ void mma_fp16(float* c, const uint32_t* a, uint32_t b0, uint32_t b1) {
    asm volatile(
        "mma.sync.aligned.m16n8k16.row.col.f32.f16.f16.f32 "
        "{%0,%1,%2,%3}, {%4,%5,%6,%7}, {%8,%9}, {%0,%1,%2,%3};"
        : "+f"(c[0]), "+f"(c[1]), "+f"(c[2]), "+f"(c[3])
        : "r"(a[0]), "r"(a[1]), "r"(a[2]), "r"(a[3]), "r"(b0), "r"(b1));
}

// ---------------- K_pre_w: params -> fp16; zero scratch; c2 ----------------
__global__ void kpw(const float* __restrict__ w, const float* __restrict__ cw) {
    int i = blockIdx.x * blockDim.x + threadIdx.x;
    if (i < CC * CC) g_wh[i] = __float2half(w[i]);
    if (i < KK * CC) g_cwh[i] = __float2half(cw[i]);
    if (i < BB * KK * CC) g_enc[i] = 0.f;
    if (i < BB * KK)      g_asum[i] = 0.f;
    if (i < KK) {
        const float* p = cw + (size_t)i * CC;
        float s = 0.f;
        for (int c = 0; c < CC; c++) { float v = p[c]; s = fmaf(v, v, s); }
        g_c2[i] = s;
    }
}

// ---------------- K_pre_x: transpose x (b,c,n)->(b,n,c) + fp16, half2 writes ----------------
__global__ void __launch_bounds__(256) kpx(const float* __restrict__ x) {
    __shared__ float t[64][33];
    int tid = threadIdx.x;
    int lane = tid & 31, w = tid >> 5;
    int b = blockIdx.z;
    int cb = blockIdx.y * 64;
    int nb = blockIdx.x * 32;
    const float* xb = x + (size_t)b * CC * HWN;
#pragma unroll
    for (int it = 0; it < 8; it++) {
        int r = w + it * 8;
        t[r][lane] = xb[(size_t)(cb + r) * HWN + nb + lane];
    }
    __syncthreads();
#pragma unroll
    for (int it = 0; it < 4; it++) {
        int idx = tid + it * 256;
        int n = idx >> 5;
        int cp = idx & 31;
        __half2 h = __floats2half2_rn(t[2 * cp][n], t[2 * cp + 1][n]);
        *(__half2*)&g_xh[((size_t)b * HWN + nb + n) * CC + cb + 2 * cp] = h;
    }
}

// ---------------- K1F: X-resident fused GEMM + BN2 + relu + xc + softmax -> feats, asnT, asum ----
// 512 CTAs, 1/SM. X tile (128px x 512c) resident in smem; W streamed (8KB chunks, L2-hot).
// Loops 4 output-channel slices; xc accumulators persist in regs; softmax fused at end.
#define OFF_BNS 0
#define OFF_BNH 2048
#define OFF_X2S 4096
#define OFF_C2S 4608
#define OFF_SCS 4736
#define OFF_XCS 4864                   // float[128][33] = 16896 -> 21760
#define OFF_W   22528                  // 3 * 8192 -> 47104
#define OFF_CW  47104                  // 8192 -> 55296
#define OFF_FT  55296                  // 32768 -> 88064  (asn overlays here post-use)
#define OFF_XT  88064                  // 131072 -> 219136
#define SMEM_K1F 219136

__global__ void __launch_bounds__(256, 1) k1f(
    const float* __restrict__ g2, const float* __restrict__ b2,
    const float* __restrict__ m2, const float* __restrict__ v2,
    const float* __restrict__ scale)
{
    extern __shared__ char sm[];
    uint32_t sb = smem_u32(sm);
    int tid = threadIdx.x;
    int lane = tid & 31;
    int wid = tid >> 5;
    int warp_m = wid >> 1;
    int warp_n = wid & 1;
    int m0 = blockIdx.x * 128;          // global pixel base (b*HWN + n)
    int b = m0 >> 12;
    int n0px = m0 & (HWN - 1);

    float* bns = (float*)(sm + OFF_BNS);
    float* bnh = (float*)(sm + OFF_BNH);
    float* x2s = (float*)(sm + OFF_X2S);
    float* c2s = (float*)(sm + OFF_C2S);
    float* scs = (float*)(sm + OFF_SCS);
    float (*xcs)[33] = (float(*)[33])(sm + OFF_XCS);

    // issue X tile: 8 subtiles of (128 rows x 64 c), swz128, group 0
    const __half* xh = g_xh + (size_t)m0 * CC;
#pragma unroll
    for (int it = 0; it < 32; it++) {
        int idx = tid + it * 256;       // 0..8191
        int cs = idx >> 10;             // 0..7
        int row = (idx >> 3) & 127;
        int seg = idx & 7;
        cpasync16(sb + OFF_XT + cs * 16384 + swz128((uint32_t)(row * 128 + seg * 16)),
                  xh + (size_t)row * CC + cs * 64 + seg * 8);
    }
    CP_COMMIT();

    // W stage issuer; bundles the cw tile for og when issuing og's last stage
    auto issueW = [&](int t) {
        uint32_t base = sb + OFF_W + (t % 3) * 8192;
        int og = t >> 4, c0 = (t & 15) * 32;
#pragma unroll
        for (int it = 0; it < 2; it++) {
            int idx = tid + it * 256;
            int row = idx >> 2, seg = idx & 3;
            cpasync16(base + swz64((uint32_t)(row * 64 + seg * 16)),
                      g_wh + (size_t)(og * 128 + row) * CC + c0 + seg * 8);
        }
        if ((t & 15) == 15) {           // cw slice for this og (ready by og end)
#pragma unroll
            for (int it = 0; it < 2; it++) {
                int idx = tid + it * 256;
                int row = idx >> 4, seg = idx & 15;
                cpasync16(sb + OFF_CW + swz256((uint32_t)(row * 256 + seg * 16)),
                          g_cwh + (size_t)row * CC + og * 128 + seg * 8);
            }
        }
    };

    issueW(0); CP_COMMIT();
    issueW(1); CP_COMMIT();
    issueW(2); CP_COMMIT();

    // constants
    for (int i = tid; i < CC; i += 256) {
        float s = rsqrtf(v2[i] + EPSF) * g2[i];
        bns[i] = s;
        bnh[i] = b2[i] - m2[i] * s;
    }
    if (tid < 128) x2s[tid] = 0.f;
    if (tid < 32) { c2s[tid] = g_c2[tid]; scs[tid] = scale[tid]; }

    float c[2][8][4];
#pragma unroll
    for (int i = 0; i < 2; i++)
#pragma unroll
        for (int j = 0; j < 8; j++)
#pragma unroll
            for (int l = 0; l < 4; l++) c[i][j][l] = 0.f;
    float cc2[4][4];
#pragma unroll
    for (int i = 0; i < 4; i++)
#pragma unroll
        for (int j = 0; j < 4; j++) cc2[i][j] = 0.f;

    for (int t = 0; t < 64; t++) {
        int og = t >> 4, s = t & 15;
        int cs = s >> 1, coff = (s & 1) * 64;
        CP_WAIT2();
        __syncthreads();
        uint32_t tbW = sb + OFF_W + (t % 3) * 8192;
#pragma unroll
        for (int kk = 0; kk < 2; kk++) {
            uint32_t bfr[4][4], a2[2][4];
#pragma unroll
            for (int ng = 0; ng < 4; ng++) {
                uint32_t off = swz64((uint32_t)((warp_n * 64 + ng * 16 + (lane & 15)) * 64
                                               + kk * 32 + (lane >> 4) * 16));
                ldsm4(tbW + off, bfr[ng]);
            }
#pragma unroll
            for (int mt = 0; mt < 2; mt++) {
                uint32_t off = swz128((uint32_t)((warp_m * 32 + mt * 16 + (lane & 15)) * 128
                                                + coff + kk * 32 + (lane >> 4) * 16));
                ldsm4(sb + OFF_XT + cs * 16384 + off, a2[mt]);
            }
#pragma unroll
            for (int mt = 0; mt < 2; mt++)
#pragma unroll
                for (int ng = 0; ng < 4; ng++)
#pragma unroll
                    for (int h = 0; h < 2; h++)
                        mma_fp16(c[mt][ng * 2 + h], a2[mt], bfr[ng][h], bfr[ng][h + 2]);
        }
        __syncthreads();
        if (t + 3 < 64) issueW(t + 3);
        CP_COMMIT();

        if (s == 15) {
            // ---- epilogue for og: BN + relu -> g_fh + FT smem; x2 smem atomics ----
#pragma unroll
            for (int mt = 0; mt < 2; mt++) {
                int rl0 = warp_m * 32 + mt * 16 + (lane >> 2);
                int r0 = m0 + rl0;
                float q0 = 0.f, q1 = 0.f;
#pragma unroll
                for (int j = 0; j < 8; j++) {
                    int cl = warp_n * 64 + j * 8 + (lane & 3) * 2;
                    int cg = og * 128 + cl;
                    float s0 = bns[cg], h0 = bnh[cg];
                    float s1 = bns[cg + 1], h1 = bnh[cg + 1];
                    float v00 = fmaxf(fmaf(c[mt][j][0], s0, h0), 0.f);
                    float v01 = fmaxf(fmaf(c[mt][j][1], s1, h1), 0.f);
                    float v10 = fmaxf(fmaf(c[mt][j][2], s0, h0), 0.f);
                    float v11 = fmaxf(fmaf(c[mt][j][3], s1, h1), 0.f);
                    __half2 p0 = __floats2half2_rn(v00, v01);
                    __half2 p1 = __floats2half2_rn(v10, v11);
                    *(__half2*)&g_fh[(size_t)r0 * CC + cg] = p0;
                    *(__half2*)&g_fh[(size_t)(r0 + 8) * CC + cg] = p1;
                    *(__half2*)(sm + OFF_FT + swz128((uint32_t)(rl0 * 128 + cl * 2))) = p0;
                    *(__half2*)(sm + OFF_FT + swz128((uint32_t)((rl0 + 8) * 128 + cl * 2))) = p1;
                    float2 f0 = __half22float2(p0);
                    float2 f1 = __half22float2(p1);
                    q0 = fmaf(f0.x, f0.x, fmaf(f0.y, f0.y, q0));
                    q1 = fmaf(f1.x, f1.x, fmaf(f1.y, f1.y, q1));
                }
                q0 += __shfl_xor_sync(0xffffffffu, q0, 1);
                q0 += __shfl_xor_sync(0xffffffffu, q0, 2);
                q1 += __shfl_xor_sync(0xffffffffu, q1, 1);
                q1 += __shfl_xor_sync(0xffffffffu, q1, 2);
                if ((lane & 3) == 0) {
                    atomicAdd(&x2s[rl0], q0);
                    atomicAdd(&x2s[rl0 + 8], q1);
                }
            }
            __syncthreads();
            // ---- xc partial mma for og (accumulate cc2 across og) ----
#pragma unroll
            for (int kk = 0; kk < 8; kk++) {
                uint32_t a[4], b0[4], b1[4];
                ldsm4(sb + OFF_FT + swz128((uint32_t)((wid * 16 + (lane & 15)) * 128
                                                     + kk * 32 + (lane >> 4) * 16)), a);
                ldsm4(sb + OFF_CW + swz256((uint32_t)((lane & 15) * 256 + kk * 32 + (lane >> 4) * 16)), b0);
                ldsm4(sb + OFF_CW + swz256((uint32_t)((16 + (lane & 15)) * 256 + kk * 32 + (lane >> 4) * 16)), b1);
#pragma unroll
                for (int h = 0; h < 2; h++) {
                    mma_fp16(cc2[h],     a, b0[h], b0[h + 2]);
                    mma_fp16(cc2[2 + h], a, b1[h], b1[h + 2]);
                }
            }
            // reset main accumulators for next og
#pragma unroll
            for (int i = 0; i < 2; i++)
#pragma unroll
                for (int j = 0; j < 8; j++)
#pragma unroll
                    for (int l = 0; l < 4; l++) c[i][j][l] = 0.f;
        }
    }

    // ---- scatter xc to smem (each element written by exactly one thread) ----
    {
        int q = lane & 3, r = lane >> 2;
#pragma unroll
        for (int half = 0; half < 2; half++) {
            int pxl = wid * 16 + r + half * 8;
#pragma unroll
            for (int g = 0; g < 4; g++)
#pragma unroll
                for (int e = 0; e < 2; e++)
                    xcs[pxl][g * 8 + q * 2 + e] = cc2[g][half * 2 + e];
        }
    }
    __syncthreads();

    // ---- softmax per pixel (tid < 128), asn overlay at OFF_FT ----
    __half (*asn)[136] = (__half(*)[136])(sm + OFF_FT);
    if (tid < 128) {
        float x2v = x2s[tid];
        float d[32], mx = -1e30f;
#pragma unroll
        for (int k = 0; k < 32; k++) {
            d[k] = scs[k] * (x2v - 2.f * xcs[tid][k] + c2s[k]);
            mx = fmaxf(mx, d[k]);
        }
        float se = 0.f;
#pragma unroll
        for (int k = 0; k < 32; k++) { d[k] = __expf(d[k] - mx); se += d[k]; }
        float inv = 1.f / se;
#pragma unroll
        for (int k = 0; k < 32; k++)
            asn[k][tid] = __float2half(d[k] * inv);
    }
    __syncthreads();

    // ---- asum ----
    {
        int k = tid >> 3, seg = tid & 7;
        float s = 0.f;
#pragma unroll
        for (int j = 0; j < 16; j++)
            s += __half2float(asn[k][seg * 16 + j]);
        s += __shfl_xor_sync(0xffffffffu, s, 1);
        s += __shfl_xor_sync(0xffffffffu, s, 2);
        s += __shfl_xor_sync(0xffffffffu, s, 4);
        if (seg == 0) atomicAdd(&g_asum[b * KK + k], s);
    }
    // ---- asn^T global write ----
#pragma unroll
    for (int it = 0; it < 2; it++) {
        int idx = tid + it * 256;
        int row = idx >> 4, cs16 = idx & 15;
        uint4 v = *(const uint4*)&asn[row][cs16 * 8];
        *(uint4*)&g_asnT[((size_t)b * KK + row) * HWN + n0px + cs16 * 8] = v;
    }
}

// ---------------- K3: HMMA encoded^T[c][k] = feats^T @ assign^T, atomic acc ----------------
#define K3_STG 20480
__global__ void __launch_bounds__(256) k3_agg()
{
    __shared__ __align__(16) char st[3 * K3_STG];
    uint32_t sb = smem_u32(st);
    int tid = threadIdx.x, lane = tid & 31, w = tid >> 5;
    int b = blockIdx.z;
    int c0 = blockIdx.x * 128;
    int n0 = blockIdx.y * (HWN / NSPLIT);
    size_t m0 = (size_t)b * HWN + n0;

    auto issue = [&](int ch) {
        uint32_t base = sb + (ch % 3) * K3_STG;
#pragma unroll
        for (int it = 0; it < 4; it++) {
            int idx = tid + it * 256;
            int row = idx >> 4, seg = idx & 15;
            cpasync16(base + swz256((uint32_t)(row * 256 + seg * 16)),
                      g_fh + (m0 + ch * 64 + row) * CC + c0 + seg * 8);
        }
        {
            int row = tid >> 3, seg = tid & 7;
            cpasync16(base + 16384 + swz128((uint32_t)(row * 128 + seg * 16)),
                      g_asnT + ((size_t)b * KK + row) * HWN + n0 + ch * 64 + seg * 8);
        }
    };
    issue(0); CP_COMMIT(); issue(1); CP_COMMIT(); issue(2); CP_COMMIT();

    float c[4][4];
#pragma unroll
    for (int i = 0; i < 4; i++)
#pragma unroll
        for (int j = 0; j < 4; j++) c[i][j] = 0.f;

    for (int ch = 0; ch < 8; ch++) {
        CP_WAIT2();
        __syncthreads();
        uint32_t tb = sb + (ch % 3) * K3_STG;
#pragma unroll
        for (int kk = 0; kk < 4; kk++) {
            uint32_t a[4], b0[4], b1[4];
            int arow = kk * 16 + ((lane >> 4) << 3) + (lane & 7);
            int acol = w * 16 + (((lane >> 3) & 1) << 3);
            ldsm4t(tb + swz256((uint32_t)(arow * 256 + acol * 2)), a);
            ldsm4(tb + 16384 + swz128((uint32_t)((lane & 15) * 128 + kk * 32 + (lane >> 4) * 16)), b0);
            ldsm4(tb + 16384 + swz128((uint32_t)((16 + (lane & 15)) * 128 + kk * 32 + (lane >> 4) * 16)), b1);
#pragma unroll
            for (int h = 0; h < 2; h++) {
                mma_fp16(c[h],     a, b0[h], b0[h + 2]);
                mma_fp16(c[2 + h], a, b1[h], b1[h + 2]);
            }
        }
        __syncthreads();
        if (ch + 3 < 8) issue(ch + 3);
        CP_COMMIT();
    }

    int q = lane & 3, r = lane >> 2;
#pragma unroll
    for (int half = 0; half < 2; half++) {
        int cr = c0 + w * 16 + r + half * 8;
#pragma unroll
        for (int g = 0; g < 4; g++)
#pragma unroll
            for (int e = 0; e < 2; e++) {
                int k = g * 8 + q * 2 + e;
                atomicAdd(&g_enc[((size_t)b * KK + k) * CC + cr], c[g][half * 2 + e]);
            }
    }
}

// ---------------- K45: ef (BN1+relu+mean) then gamma = sigmoid(fc) ----------------
__global__ void __launch_bounds__(512) k45(
    const float* __restrict__ cw, const float* __restrict__ g1,
    const float* __restrict__ b1, const float* __restrict__ m1,
    const float* __restrict__ v1,
    const float* __restrict__ fcw, const float* __restrict__ fcb,
    float* __restrict__ ef_out)
{
    __shared__ float efs[CC];
    int b = blockIdx.x;
    int o = threadIdx.x;
    float s = 0.f;
#pragma unroll
    for (int k = 0; k < KK; k++) {
        float e = g_enc[((size_t)b * KK + k) * CC + o] - g_asum[b * KK + k] * cw[(size_t)k * CC + o];
        float sc = rsqrtf(v1[k] + EPSF) * g1[k];
        e = fmaf(e - m1[k], sc, b1[k]);
        e = fmaxf(e, 0.f);
        s += e;
    }
    float ef = s * (1.f / KK);
    efs[o] = ef;
    ef_out[b * CC + o] = ef;
    __syncthreads();

    const float* wr = fcw + (size_t)o * CC;
    float g = fcb[o];
#pragma unroll 8
    for (int c = 0; c < CC; c += 4) {
        float4 w4 = *(const float4*)&wr[c];
        g = fmaf(w4.x, efs[c + 0], g);
        g = fmaf(w4.y, efs[c + 1], g);
        g = fmaf(w4.z, efs[c + 2], g);
        g = fmaf(w4.w, efs[c + 3], g);
    }
    g_gamma[b * CC + o] = 1.f / (1.f + __expf(-g));
}

// ---------------- K6: output = relu(x*(1+gamma)) reading fp16 x^T (smem transpose) ----------------
__global__ void __launch_bounds__(256) k6_out(float* __restrict__ out)
{
    __shared__ __align__(16) __half t[64 * 64];
    int tid = threadIdx.x;
    int b  = blockIdx.z;
    int cb = blockIdx.y * 64;
    int nb = blockIdx.x * 64;

#pragma unroll
    for (int it = 0; it < 2; it++) {
        int idx = tid + it * 256;
        int n = idx >> 3, seg = idx & 7;
        int phys = seg ^ ((n >> 2) & 7);
        uint4 v = *(const uint4*)&g_xh[((size_t)b * HWN + nb + n) * CC + cb + seg * 8];
        *(uint4*)&t[n * 64 + phys * 8] = v;
    }
    __syncthreads();

#pragma unroll
    for (int it = 0; it < 4; it++) {
        int idx = tid + it * 256;
        int c = idx >> 4;
        int nb4 = (idx & 15) * 4;
        float g = 1.f + g_gamma[b * CC + cb + c];
        int seg = c >> 3, coff = c & 7;
        float4 o;
        float* op = &o.x;
#pragma unroll
        for (int dn = 0; dn < 4; dn++) {
            int n = nb4 + dn;
            int phys = seg ^ ((n >> 2) & 7);
            float v = __half2float(t[n * 64 + phys * 8 + coff]);
            op[dn] = fmaxf(v * g, 0.f);
        }
        *(float4*)&out[((size_t)b * CC + cb + c) * HWN + nb + nb4] = o;
    }
}

// ---------------- launch ----------------
extern "C" void kernel_launch(void* const* d_in, const int* in_sizes, int n_in,
                              void* d_out, int out_size)
{
    const float* x      = (const float*)d_in[0];
    const float* conv_w = (const float*)d_in[1];
    const float* bn2_g  = (const float*)d_in[2];
    const float* bn2_b  = (const float*)d_in[3];
    const float* bn2_m  = (const float*)d_in[4];
    const float* bn2_v  = (const float*)d_in[5];
    const float* cw     = (const float*)d_in[6];
    const float* scale  = (const float*)d_in[7];
    const float* bn1_g  = (const float*)d_in[8];
    const float* bn1_b  = (const float*)d_in[9];
    const float* bn1_m  = (const float*)d_in[10];
    const float* bn1_v  = (const float*)d_in[11];
    const float* fc_w   = (const float*)d_in[12];
    const float* fc_b   = (const float*)d_in[13];
    float* out = (float*)d_out;   // [0:8192) encoding_feat, [8192:) output

    static bool attr_set = false;
    if (!attr_set) {
        cudaFuncSetAttribute(k1f, cudaFuncAttributeMaxDynamicSharedMemorySize, SMEM_K1F);
        attr_set = true;
    }

    kpw<<<(CC * CC + 255) / 256, 256>>>(conv_w, cw);

    dim3 gpx(HWN / 32, CC / 64, BB);
    kpx<<<gpx, 256>>>(x);

    k1f<<<BB * HWN / 128, 256, SMEM_K1F>>>(bn2_g, bn2_b, bn2_m, bn2_v, scale);

    dim3 g3(CC / 128, NSPLIT, BB);
    k3_agg<<<g3, 256>>>();

    k45<<<BB, 512>>>(cw, bn1_g, bn1_b, bn1_m, bn1_v, fc_w, fc_b, out);

    dim3 g6(HWN / 64, CC / 64, BB);
    k6_out<<<g6, 256>>>(out + BB * CC);
}